// round 17
// baseline (speedup 1.0000x reference)
#include <cuda_runtime.h>
#include <cstdint>

// ---------------- problem constants ----------------
#define NPIX   65536            // 256*256
#define LOf    (-3.0f)
#define Hstep  (6.0f / 63.0f)   // linspace(-3,3,64) spacing
#define A2     (4.0e-4f)        // FALL_OFF^2
#define EPSf   (1e-6f)
#define SCALE  64.0f            // fp16 range management; cancels in normalization

// ---------------- tiling ---------------------------
#define NIB    16               // (img,batch): 2*8
#define NCH    128              // chunks per (img,batch)
#define KPIX   512              // pixels per block
#define SPX    64               // pixels per stage (mma K-window)
#define NSTG   (KPIX / SPX)     // 8
#define NBLK   (NIB * NCH)      // 2048

// SMEM layout (dynamic, 57344 B):
//   [0, 8192):  s1,s2,s3,siy  (4 x 512 f32)
//   [8192 + buf*24576 + j*8192): W_j stage matrix, 64 bins x 64 px fp16,
//       128 B rows, SW128 xor-swizzle ((row&7)<<4)
#define SMEM_SZ   57344
#define W_OFF     8192
#define W_BUFSTR  24576

// ---------------- static scratch -------------------
__device__ float g_partial[NBLK][3 * 4096];   // ~100 MB
__device__ float g_hist[NIB][3 * 4096];
__device__ float g_hb[8];

// ---------------- helpers --------------------------
__device__ __forceinline__ uint32_t smem_u32(const void* p) {
    uint32_t a;
    asm("{ .reg .u64 t; cvta.to.shared.u64 t, %1; cvt.u32.u64 %0, t; }" : "=r"(a) : "l"(p));
    return a;
}
__device__ __forceinline__ float frcp(float q) {
    float r;
    asm("rcp.approx.f32 %0, %1;" : "=f"(r) : "f"(q));
    return r;
}
#define STS32(addr, val) \
    asm volatile("st.shared.b32 [%0], %1;" :: "r"(addr), "r"(val) : "memory")

#define LDSM4(r0, r1, r2, r3, addr) \
    asm volatile("ldmatrix.sync.aligned.m8n8.x4.shared.b16 {%0,%1,%2,%3}, [%4];" \
        : "=r"(r0), "=r"(r1), "=r"(r2), "=r"(r3) : "r"(addr))

#define MMA4(d, a, b0, b1) \
    asm volatile("mma.sync.aligned.m16n8k16.row.col.f32.f16.f16.f32 " \
        "{%0,%1,%2,%3}, {%4,%5,%6,%7}, {%8,%9}, {%0,%1,%2,%3};" \
        : "+f"((d)[0]), "+f"((d)[1]), "+f"((d)[2]), "+f"((d)[3]) \
        : "r"((a)[0]), "r"((a)[1]), "r"((a)[2]), "r"((a)[3]), "r"(b0), "r"(b1))

// one pixel-pair weight eval + packed fp16 store (identical math to R13)
__device__ __forceinline__ void gen_pair(
    const float* S, const float* siy, int px, float ck, uint32_t addr)
{
    float2 sv = *(const float2*)(S + px);
    float2 yv = *(const float2*)(siy + px);
    float d0 = sv.x - ck, d1 = sv.y - ck;
    float w0 = yv.x * frcp(fmaf(d0, d0, A2));
    float w1 = yv.y * frcp(fmaf(d1, d1, A2));
    uint32_t pk;
    asm("cvt.rn.f16x2.f32 %0, %1, %2;" : "=r"(pk) : "f"(w1), "f"(w0));
    STS32(addr, pk);
}

// =====================================================================
// weight generation for one 64-px stage (gen warps: 128 threads).
// thread u in [0,128): gp = u>>6, k = u&63.
//   gp=0: full row (j=0, k) 32 pairs + half row (j=2, k) pairs 0..15
//   gp=1: full row (j=1, k) 32 pairs + half row (j=2, k) pairs 16..31
// rotation 5*m (m=(k>>3)&3): pair-index diffs {5,10,15} are never 0 mod 4,
// so STS banks (ppr ^ ((k&7)<<2)) are conflict-free across the warp.
// =====================================================================
__device__ __forceinline__ void gen_stage(
    int st, uint32_t wb, const float* s1, const float* s2, const float* s3,
    const float* siy, int gp, int k, float ck)
{
    const int sb = st * SPX;
    const uint32_t kxor = (uint32_t)(k & 7) << 4;
    const int rot = 5 * ((k >> 3) & 3);

    const float* Sf = gp ? s2 : s1;
    const uint32_t rowf = wb + (uint32_t)gp * 8192u + (uint32_t)k * 128u;
    #pragma unroll 8
    for (int pp = 0; pp < 32; pp++) {
        const int ppr = (pp + rot) & 31;
        gen_pair(Sf, siy, sb + 2 * ppr, ck, rowf + (((uint32_t)(4 * ppr)) ^ kxor));
    }

    const uint32_t rowh = wb + 2u * 8192u + (uint32_t)k * 128u;
    const int hbase = gp * 16;
    #pragma unroll 8
    for (int pp = 0; pp < 16; pp++) {
        const int ppr = hbase + ((pp + rot) & 15);
        gen_pair(s3, siy, sb + 2 * ppr, ck, rowh + (((uint32_t)(4 * ppr)) ^ kxor));
    }
}

// =====================================================================
// K1: warp-specialized tensor-core histogram.
//   warps 0-3: MMA, 2x2 grid of 32x32 tiles, all 3 channels
//   warps 4-7: weight generation (double-buffered stages)
//   a_j[k][px] = SCALE*sqrt(iy)*A2*rcp((d_j-c_k)^2+A2)  (fp16)
//   H_r = a1*a2^T; H_g[u,v] = (a1*a3^T)[63-u,v]; H_b[u,v] = (a2*a3^T)[63-u,63-v]
// =====================================================================
__global__ void __launch_bounds__(256, 1) hist_kernel(const float* __restrict__ x,
                                                      const float* __restrict__ y) {
    extern __shared__ __align__(16) unsigned char smem_raw[];
    float* s1  = (float*)smem_raw;
    float* s2  = s1 + KPIX;
    float* s3  = s2 + KPIX;
    float* siy = s3 + KPIX;
    const uint32_t smb = smem_u32(smem_raw);

    const int t  = threadIdx.x;
    const int bx = blockIdx.x;
    const int ib    = bx >> 7;               // 0..15
    const int chunk = bx & (NCH - 1);
    const float* base = (ib < 8 ? x : y) + (size_t)(ib & 7) * 3 * NPIX + chunk * KPIX;

    // ---- prep: chroma diffs + scaled sqrt-intensity (all threads) ----
    {
        const int p = 2 * t;
        float2 c0 = *(const float2*)(base + p);
        float2 c1 = *(const float2*)(base + NPIX + p);
        float2 c2 = *(const float2*)(base + 2 * NPIX + p);
        float a0[2] = {c0.x, c0.y}, a1[2] = {c1.x, c1.y}, a2v[2] = {c2.x, c2.y};
        #pragma unroll
        for (int j = 0; j < 2; j++) {
            float v0 = a0[j] + EPSf, v1 = a1[j] + EPSf, v2 = a2v[j] + EPSf;
            float l0 = __logf(v0), l1 = __logf(v1), l2 = __logf(v2);
            s1[p + j] = l0 - l1;             // d1 = lr - lg
            s2[p + j] = l0 - l2;             // d2 = lr - lb
            s3[p + j] = l1 - l2;             // d3 = lg - lb
            float ss = fmaf(v0, v0, fmaf(v1, v1, v2 * v2));
            siy[p + j] = (SCALE * A2) * sqrtf(sqrtf(ss));   // SCALE*sqrt(iy)*A2
        }
    }

    const int w = t >> 5, lane = t & 31;
    const bool is_mma = (w < 4);

    // gen role (warps 4-7): u in [0,128)
    const int u  = t - 128;
    const int gp = (u >> 6) & 1;
    const int k  = u & 63;
    const float ck = fmaf((float)k, Hstep, LOf);

    // mma role (warps 0-3): 2x2 grid of 32x32 tiles
    const int ti = (w >> 1) & 1;             // row-tile
    const int tj = w & 1;                    // col-tile
    const int rr = lane & 7;
    const uint32_t arow = (uint32_t)(32 * ti + rr + 8 * ((lane >> 3) & 1)) * 128u;
    const uint32_t akh  = (uint32_t)(lane >> 4) * 16u;
    const uint32_t brow = (uint32_t)(32 * tj + rr + 8 * (lane >> 4)) * 128u;
    const uint32_t bkh  = (uint32_t)((lane >> 3) & 1) * 16u;
    const uint32_t sxor = (uint32_t)rr << 4;

    float ar[2][16] = {}, ag[2][16] = {}, ab[2][16] = {};   // [m][4*nf+e]

    __syncthreads();
    if (!is_mma) gen_stage(0, smb + W_OFF, s1, s2, s3, siy, gp, k, ck);
    __syncthreads();

    for (int st = 0; st < NSTG; st++) {
        const uint32_t wb = smb + W_OFF + (uint32_t)(st & 1) * W_BUFSTR;
        if (is_mma) {
            const uint32_t w1b = wb, w2b = wb + 8192u, w3b = wb + 16384u;
            #pragma unroll
            for (int ks = 0; ks < 4; ks++) {
                const uint32_t offA = (32u * ks + akh) ^ sxor;
                const uint32_t offB = (32u * ks + bkh) ^ sxor;
                uint32_t A1[2][4], A2f[2][4], B2[8], B3[8];
                LDSM4(A1[0][0], A1[0][1], A1[0][2], A1[0][3],     w1b + arow + offA);
                LDSM4(A1[1][0], A1[1][1], A1[1][2], A1[1][3],     w1b + arow + 2048u + offA);
                LDSM4(A2f[0][0], A2f[0][1], A2f[0][2], A2f[0][3], w2b + arow + offA);
                LDSM4(A2f[1][0], A2f[1][1], A2f[1][2], A2f[1][3], w2b + arow + 2048u + offA);
                LDSM4(B2[0], B2[1], B2[2], B2[3],                 w2b + brow + offB);
                LDSM4(B2[4], B2[5], B2[6], B2[7],                 w2b + brow + 2048u + offB);
                LDSM4(B3[0], B3[1], B3[2], B3[3],                 w3b + brow + offB);
                LDSM4(B3[4], B3[5], B3[6], B3[7],                 w3b + brow + 2048u + offB);
                #pragma unroll
                for (int m = 0; m < 2; m++) {
                    #pragma unroll
                    for (int nf = 0; nf < 4; nf++) {
                        MMA4(&ar[m][4 * nf], A1[m],  B2[2 * nf], B2[2 * nf + 1]);
                        MMA4(&ag[m][4 * nf], A1[m],  B3[2 * nf], B3[2 * nf + 1]);
                        MMA4(&ab[m][4 * nf], A2f[m], B3[2 * nf], B3[2 * nf + 1]);
                    }
                }
            }
        } else if (st + 1 < NSTG) {
            gen_stage(st + 1, smb + W_OFF + (uint32_t)((st & 1) ^ 1) * W_BUFSTR,
                      s1, s2, s3, siy, gp, k, ck);
        }
        __syncthreads();
    }

    // ---- epilogue (mma warps): store with channel bin-reversal folded in ----
    if (is_mma) {
        float* op = g_partial[bx];
        const int r = lane >> 2, c = 2 * (lane & 3);
        #pragma unroll
        for (int m = 0; m < 2; m++) {
            const int u0 = 32 * ti + 16 * m + r;
            const int u1 = u0 + 8;
            #pragma unroll
            for (int nf = 0; nf < 4; nf++) {
                const int col = 32 * tj + 8 * nf + c;
                const float* fr = &ar[m][4 * nf];
                const float* fg = &ag[m][4 * nf];
                const float* fb = &ab[m][4 * nf];
                *(float2*)&op[u0 * 64 + col] = make_float2(fr[0], fr[1]);
                *(float2*)&op[u1 * 64 + col] = make_float2(fr[2], fr[3]);
                *(float2*)&op[4096 + (63 - u0) * 64 + col] = make_float2(fg[0], fg[1]);
                *(float2*)&op[4096 + (63 - u1) * 64 + col] = make_float2(fg[2], fg[3]);
                *(float2*)&op[8192 + (63 - u0) * 64 + (62 - col)] = make_float2(fb[1], fb[0]);
                *(float2*)&op[8192 + (63 - u1) * 64 + (62 - col)] = make_float2(fb[3], fb[2]);
            }
        }
    }
}

// =====================================================================
// K2: reduce 128 chunk partials per (img,batch)
// =====================================================================
__global__ void __launch_bounds__(256) reduce_kernel() {
    const int ib  = blockIdx.x / 24;
    const int seg = blockIdx.x % 24;
    const int e0  = seg * 512;
    for (int e = e0 + threadIdx.x; e < e0 + 512; e += 256) {
        float s = 0.0f;
        #pragma unroll 8
        for (int c = 0; c < NCH; c++)
            s += g_partial[ib * NCH + c][e];
        g_hist[ib][e] = s;
    }
}

// =====================================================================
// K3: per-batch totals + Hellinger-style distance
// =====================================================================
__global__ void __launch_bounds__(256) loss_kernel() {
    const int b = blockIdx.x;
    const int t = threadIdx.x;
    __shared__ float rx[256], ry[256];

    float sx = 0.0f, sy = 0.0f;
    for (int e = t; e < 3 * 4096; e += 256) {
        sx += g_hist[b][e];
        sy += g_hist[8 + b][e];
    }
    rx[t] = sx; ry[t] = sy;
    __syncthreads();
    for (int s2 = 128; s2 > 0; s2 >>= 1) {
        if (t < s2) { rx[t] += rx[t + s2]; ry[t] += ry[t + s2]; }
        __syncthreads();
    }
    const float itx = 1.0f / rx[0];
    const float ity = 1.0f / ry[0];
    __syncthreads();

    float hs = 0.0f;
    for (int e = t; e < 3 * 4096; e += 256) {
        float d = sqrtf(g_hist[8 + b][e] * ity) - sqrtf(g_hist[b][e] * itx);
        hs = fmaf(d, d, hs);
    }
    rx[t] = hs;
    __syncthreads();
    for (int s2 = 128; s2 > 0; s2 >>= 1) {
        if (t < s2) rx[t] += rx[t + s2];
        __syncthreads();
    }
    if (t == 0) g_hb[b] = rx[0];
}

// =====================================================================
// K4: final scalar — mean over batch of sqrt(0.5 * h_b)
// =====================================================================
__global__ void final_kernel(float* __restrict__ out) {
    if (threadIdx.x == 0) {
        float s = 0.0f;
        for (int b = 0; b < 8; b++)
            s += sqrtf(g_hb[b] * 0.5f);
        out[0] = s * 0.125f;
    }
}

// =====================================================================
extern "C" void kernel_launch(void* const* d_in, const int* in_sizes, int n_in,
                              void* d_out, int out_size) {
    const float* x = (const float*)d_in[0];
    const float* y = (const float*)d_in[1];

    cudaFuncSetAttribute(hist_kernel, cudaFuncAttributeMaxDynamicSharedMemorySize, SMEM_SZ);
    hist_kernel<<<NBLK, 256, SMEM_SZ>>>(x, y);
    reduce_kernel<<<NIB * 24, 256>>>();
    loss_kernel<<<8, 256>>>();
    final_kernel<<<1, 32>>>((float*)d_out);
}